// round 8
// baseline (speedup 1.0000x reference)
#include <cuda_runtime.h>
#include <math.h>

#define B    32
#define C    3
#define H    640
#define W    640
#define POOL 8
#define BLK  80                  // H/POOL = rows per pool-row block
#define HW   (H * W)             // 409600
#define HIDDEN 64
#define FEAT   (C * POOL * POOL) // 192
#define NPARAM (C * C + 2 * C)   // 15

#define W4      (W / 4)          // 160 float4 per image row
#define ROWGRPS 2                // row-groups per CTA pass
#define PTHREADS (ROWGRPS * W4)  // 320 threads in pool kernel
#define PGRID   (B * C * POOL)   // 768 CTAs

// Scratch (no allocations allowed)
__device__ float g_pooled[B * FEAT];
__device__ float g_params[B * NPARAM];
__device__ unsigned int g_ticket;   // zero-init; last CTA resets -> replay-safe

__constant__ float c_mean[3]    = {0.485f, 0.456f, 0.406f};
__constant__ float c_invstd[3]  = {1.0f / 0.229f, 1.0f / 0.224f, 1.0f / 0.225f};

// Guaranteed-MUFU fast pow for strictly-positive base: 2^(g * log2(x))
__device__ __forceinline__ float fast_pow_pos(float x, float g)
{
    float l, r;
    asm("lg2.approx.f32 %0, %1;" : "=f"(l) : "f"(x));
    l *= g;
    asm("ex2.approx.f32 %0, %1;" : "=f"(r) : "f"(l));
    return r;
}

// -------------------------------------------------------------------------
// Kernel 1: block means + (last CTA) whole-batch MLP.
// One CTA per (b, ch, pool_row): 80 rows x 640 cols. 320 threads =
// 2 row-groups x 160 float4-cols; fixed column per thread; 40 loads,
// 2 accumulators for ILP. Reduce via smem + 8-thread serial sum.
// Ticket pattern: CTA drawing ticket PGRID-1 runs the 32-sample MLP.
// -------------------------------------------------------------------------
__global__ void __launch_bounds__(PTHREADS) pool_mlp_kernel(
    const float* __restrict__ x,
    const float* __restrict__ W1,
    const float* __restrict__ b1,
    const float* __restrict__ W2)
{
    const int blk = blockIdx.x;
    const int pr  = blk % POOL;
    const int ch  = (blk / POOL) % C;
    const int b   = blk / (POOL * C);
    const int tid = threadIdx.x;

    const int col4 = tid % W4;       // 0..159  (fixed per thread)
    const int rg   = tid / W4;       // 0..1    (fixed per thread)

    const float4* __restrict__ base = reinterpret_cast<const float4*>(
        x + ((size_t)(b * C + ch)) * HW + (size_t)pr * BLK * W) + (size_t)rg * W4 + col4;

    float s0 = 0.0f, s1 = 0.0f;
    #pragma unroll 8
    for (int r = 0; r < BLK / ROWGRPS; r += 2) {   // 40 rows -> 20 pairs
        float4 a = base[(size_t)r       * (ROWGRPS * W4)];
        float4 c = base[(size_t)(r + 1) * (ROWGRPS * W4)];
        s0 += (a.x + a.y) + (a.z + a.w);
        s1 += (c.x + c.y) + (c.z + c.w);
    }
    const float sum = s0 + s1;

    __shared__ float psum[PTHREADS];
    psum[tid] = sum;
    __syncthreads();

    if (tid < POOL) {
        // pool-col tid owns col4 in [tid*20, tid*20+20), both row-groups
        float s = 0.0f;
        #pragma unroll
        for (int g = 0; g < ROWGRPS; ++g) {
            const int base_i = g * W4 + tid * (BLK / 4);
            #pragma unroll
            for (int j = 0; j < BLK / 4; ++j)      // 20 partials
                s += psum[base_i + j];
        }
        g_pooled[b * FEAT + ch * (POOL * POOL) + pr * POOL + tid] =
            s * (1.0f / (BLK * BLK));
    }

    // ---- ticket: last CTA to finish runs the MLP over all 32 samples ----
    __syncthreads();
    __threadfence();                       // publish g_pooled writes
    __shared__ unsigned int s_ticket;
    if (tid == 0) s_ticket = atomicAdd(&g_ticket, 1u);
    __syncthreads();
    if (s_ticket != PGRID - 1) return;

    if (tid == 0) g_ticket = 0;            // reset for next graph replay
    __threadfence();                       // acquire side (order g_pooled reads)

    __shared__ float hidAll[B * HIDDEN];   // 2048 floats = 8 KB

    // layer 1: 2048 (sample, unit) dots of length 192
    for (int i = tid; i < B * HIDDEN; i += PTHREADS) {
        const int s = i / HIDDEN, u = i % HIDDEN;
        const float* __restrict__ fp = &g_pooled[s * FEAT];
        float acc = __ldg(&b1[u]);
        #pragma unroll 8
        for (int k = 0; k < FEAT; ++k)
            acc = fmaf(fp[k], __ldg(&W1[k * HIDDEN + u]), acc);
        hidAll[i] = fminf(fmaxf(acc, 0.0f), 6.0f);
    }
    __syncthreads();

    // layer 2: 480 (sample, param) dots of length 64 + sigmoid
    for (int i = tid; i < B * NPARAM; i += PTHREADS) {
        const int s = i / NPARAM, p = i % NPARAM;
        const float* __restrict__ hp = &hidAll[s * HIDDEN];
        float o = 0.0f;
        #pragma unroll 8
        for (int k = 0; k < HIDDEN; ++k)
            o = fmaf(hp[k], __ldg(&W2[k * NPARAM + p]), o);
        g_params[i] = 1.0f / (1.0f + __expf(-o));
    }
}

// -------------------------------------------------------------------------
// Kernel 2: fused color transform + pow + normalize. float4 per thread.
// Each CTA handles 256 float4 pixel-groups of a single sample (all 3 chans).
// grid = B * (HW/4/256) = 32*400 = 12800 CTAs.
// -------------------------------------------------------------------------
__global__ void __launch_bounds__(256) transform_kernel(const float* __restrict__ x,
                                                        float* __restrict__ out)
{
    const int cta_per_img = HW / 4 / 256;               // 400
    const int b  = blockIdx.x / cta_per_img;
    const int p4 = (blockIdx.x % cta_per_img) * 256 + threadIdx.x;

    __shared__ float prm[NPARAM];
    if (threadIdx.x < NPARAM) prm[threadIdx.x] = g_params[b * NPARAM + threadIdx.x];
    __syncthreads();

    const float4* __restrict__ xin =
        reinterpret_cast<const float4*>(x + (size_t)b * C * HW) + p4;
    float4* __restrict__ xo =
        reinterpret_cast<float4*>(out + (size_t)b * C * HW) + p4;

    const int c4 = HW / 4;                              // channel stride in float4
    float4 v0 = xin[0];
    float4 v1 = xin[c4];
    float4 v2 = xin[2 * c4];

    #pragma unroll
    for (int i = 0; i < C; ++i) {
        const float m0 = prm[i * 3 + 0], m1 = prm[i * 3 + 1], m2 = prm[i * 3 + 2];
        const float bi = prm[9 + i];
        const float gi = prm[12 + i];
        const float mu = c_mean[i], is = c_invstd[i];

        float4 o;
        o.x = fmaf(m0, v0.x, fmaf(m1, v1.x, fmaf(m2, v2.x, bi)));
        o.y = fmaf(m0, v0.y, fmaf(m1, v1.y, fmaf(m2, v2.y, bi)));
        o.z = fmaf(m0, v0.z, fmaf(m1, v1.z, fmaf(m2, v2.z, bi)));
        o.w = fmaf(m0, v0.w, fmaf(m1, v1.w, fmaf(m2, v2.w, bi)));

        // base > 0 always (sigmoid-weighted combo of x in [0,1) + sigmoid bias)
        o.x = (fast_pow_pos(o.x, gi) - mu) * is;
        o.y = (fast_pow_pos(o.y, gi) - mu) * is;
        o.z = (fast_pow_pos(o.z, gi) - mu) * is;
        o.w = (fast_pow_pos(o.w, gi) - mu) * is;

        xo[i * c4] = o;
    }
}

// -------------------------------------------------------------------------
extern "C" void kernel_launch(void* const* d_in, const int* in_sizes, int n_in,
                              void* d_out, int out_size)
{
    const float* x  = (const float*)d_in[0];
    const float* W1 = (const float*)d_in[1];
    const float* b1 = (const float*)d_in[2];
    const float* W2 = (const float*)d_in[3];
    float* out = (float*)d_out;

    pool_mlp_kernel<<<PGRID, PTHREADS>>>(x, W1, b1, W2);
    transform_kernel<<<B * (HW / 4 / 256), 256>>>(x, out);
}

// round 11
// speedup vs baseline: 1.3628x; 1.3628x over previous
#include <cuda_runtime.h>
#include <math.h>

#define B    32
#define C    3
#define H    640
#define W    640
#define POOL 8
#define BLK  80                  // H/POOL = rows per pool-row block
#define HW   (H * W)             // 409600
#define HIDDEN 64
#define FEAT   (C * POOL * POOL) // 192
#define NPARAM (C * C + 2 * C)   // 15

#define W4      (W / 4)          // 160 float4 per image row
#define ROWGRPS 2                // row-groups per CTA pass
#define PTHREADS (ROWGRPS * W4)  // 320 threads in pool kernel
#define PGRID   (B * C * POOL)   // 768 CTAs

// Transform tiling: 256 threads x 2 float4-groups per thread
#define TBLK      256
#define TGRP      2
#define TCHUNK    (TBLK * TGRP)          // 512 float4 per CTA
#define TCTA_IMG  (HW / 4 / TCHUNK)      // 200 CTAs per image

// Scratch (no allocations allowed)
__device__ float g_pooled[B * FEAT];
__device__ float g_params[B * NPARAM];

__constant__ float c_mean[3]    = {0.485f, 0.456f, 0.406f};
__constant__ float c_invstd[3]  = {1.0f / 0.229f, 1.0f / 0.224f, 1.0f / 0.225f};

// Guaranteed-MUFU fast pow for strictly-positive base: 2^(g * log2(x))
__device__ __forceinline__ float fast_pow_pos(float x, float g)
{
    float l, r;
    asm("lg2.approx.f32 %0, %1;" : "=f"(l) : "f"(x));
    l *= g;
    asm("ex2.approx.f32 %0, %1;" : "=f"(r) : "f"(l));
    return r;
}

// -------------------------------------------------------------------------
// Kernel 1: block means. One CTA per (b, ch, pool_row): 80 rows x 640 cols.
// 320 threads = 2 row-groups x 160 float4-cols; fixed column per thread;
// 40 loads as 20 independent pairs (2 accumulators) for ILP.
// Reduce via smem + 8-thread serial sum (deterministic, atomic-free).
// -------------------------------------------------------------------------
__global__ void __launch_bounds__(PTHREADS) pool_kernel(const float* __restrict__ x)
{
    const int blk = blockIdx.x;
    const int pr  = blk % POOL;
    const int ch  = (blk / POOL) % C;
    const int b   = blk / (POOL * C);
    const int tid = threadIdx.x;

    const int col4 = tid % W4;       // 0..159  (fixed per thread)
    const int rg   = tid / W4;       // 0..1    (fixed per thread)

    const float4* __restrict__ base = reinterpret_cast<const float4*>(
        x + ((size_t)(b * C + ch)) * HW + (size_t)pr * BLK * W) + (size_t)rg * W4 + col4;

    float s0 = 0.0f, s1 = 0.0f;
    #pragma unroll 10
    for (int r = 0; r < BLK / ROWGRPS; r += 2) {   // 40 rows -> 20 pairs
        float4 a = base[(size_t)r       * (ROWGRPS * W4)];
        float4 c = base[(size_t)(r + 1) * (ROWGRPS * W4)];
        s0 += (a.x + a.y) + (a.z + a.w);
        s1 += (c.x + c.y) + (c.z + c.w);
    }
    const float sum = s0 + s1;

    __shared__ float psum[PTHREADS];
    psum[tid] = sum;
    __syncthreads();

    if (tid < POOL) {
        // pool-col tid owns col4 in [tid*20, tid*20+20), both row-groups
        float s = 0.0f;
        #pragma unroll
        for (int g = 0; g < ROWGRPS; ++g) {
            const int base_i = g * W4 + tid * (BLK / 4);
            #pragma unroll
            for (int j = 0; j < BLK / 4; ++j)      // 20 partials
                s += psum[base_i + j];
        }
        g_pooled[b * FEAT + ch * (POOL * POOL) + pr * POOL + tid] =
            s * (1.0f / (BLK * BLK));
    }
}

// -------------------------------------------------------------------------
// Kernel 2: per-sample MLP. One CTA per sample, 64 threads.
// hid = relu6(feat @ W1 + b1);  param = sigmoid(hid @ W2)
// -------------------------------------------------------------------------
__global__ void __launch_bounds__(64) mlp_kernel(const float* __restrict__ W1,
                                                 const float* __restrict__ b1,
                                                 const float* __restrict__ W2)
{
    const int b   = blockIdx.x;
    const int tid = threadIdx.x;

    __shared__ float feat[FEAT];
    __shared__ float hid[HIDDEN];

    #pragma unroll
    for (int i = tid; i < FEAT; i += HIDDEN) feat[i] = g_pooled[b * FEAT + i];
    __syncthreads();

    // hidden unit tid: dot over 192 (W1 is [192,64] row-major -> coalesced over tid)
    float acc = __ldg(&b1[tid]);
    #pragma unroll 8
    for (int k = 0; k < FEAT; ++k)
        acc = fmaf(feat[k], __ldg(&W1[k * HIDDEN + tid]), acc);
    hid[tid] = fminf(fmaxf(acc, 0.0f), 6.0f);
    __syncthreads();

    if (tid < NPARAM) {
        float o = 0.0f;
        #pragma unroll 8
        for (int k = 0; k < HIDDEN; ++k)
            o = fmaf(hid[k], __ldg(&W2[k * NPARAM + tid]), o);
        g_params[b * NPARAM + tid] = 1.0f / (1.0f + __expf(-o));
    }
}

// -------------------------------------------------------------------------
// Kernel 3: fused color transform + pow + normalize.
// 2 float4 groups per thread (offsets tid and tid+256) -> 6 front-batched
// LDG.128, 2x MUFU/FMA ILP. grid = B * 200 = 6400 CTAs.
// -------------------------------------------------------------------------
__global__ void __launch_bounds__(TBLK) transform_kernel(const float* __restrict__ x,
                                                         float* __restrict__ out)
{
    const int b    = blockIdx.x / TCTA_IMG;
    const int base = (blockIdx.x % TCTA_IMG) * TCHUNK + threadIdx.x;

    __shared__ float prm[NPARAM];
    if (threadIdx.x < NPARAM) prm[threadIdx.x] = g_params[b * NPARAM + threadIdx.x];
    __syncthreads();

    const float4* __restrict__ xin =
        reinterpret_cast<const float4*>(x + (size_t)b * C * HW);
    float4* __restrict__ xo =
        reinterpret_cast<float4*>(out + (size_t)b * C * HW);

    const int c4 = HW / 4;                         // channel stride in float4
    const int i0 = base;
    const int i1 = base + TBLK;

    // 6 independent loads up front
    float4 a0 = xin[i0],          b0 = xin[i1];
    float4 a1 = xin[i0 + c4],     b1 = xin[i1 + c4];
    float4 a2 = xin[i0 + 2 * c4], b2 = xin[i1 + 2 * c4];

    #pragma unroll
    for (int i = 0; i < C; ++i) {
        const float m0 = prm[i * 3 + 0], m1 = prm[i * 3 + 1], m2 = prm[i * 3 + 2];
        const float bi = prm[9 + i];
        const float gi = prm[12 + i];
        const float mu = c_mean[i], is = c_invstd[i];

        float4 oa, ob;
        oa.x = fmaf(m0, a0.x, fmaf(m1, a1.x, fmaf(m2, a2.x, bi)));
        oa.y = fmaf(m0, a0.y, fmaf(m1, a1.y, fmaf(m2, a2.y, bi)));
        oa.z = fmaf(m0, a0.z, fmaf(m1, a1.z, fmaf(m2, a2.z, bi)));
        oa.w = fmaf(m0, a0.w, fmaf(m1, a1.w, fmaf(m2, a2.w, bi)));
        ob.x = fmaf(m0, b0.x, fmaf(m1, b1.x, fmaf(m2, b2.x, bi)));
        ob.y = fmaf(m0, b0.y, fmaf(m1, b1.y, fmaf(m2, b2.y, bi)));
        ob.z = fmaf(m0, b0.z, fmaf(m1, b1.z, fmaf(m2, b2.z, bi)));
        ob.w = fmaf(m0, b0.w, fmaf(m1, b1.w, fmaf(m2, b2.w, bi)));

        // base > 0 always (sigmoid-weighted combo of x in [0,1) + sigmoid bias)
        oa.x = (fast_pow_pos(oa.x, gi) - mu) * is;
        oa.y = (fast_pow_pos(oa.y, gi) - mu) * is;
        oa.z = (fast_pow_pos(oa.z, gi) - mu) * is;
        oa.w = (fast_pow_pos(oa.w, gi) - mu) * is;
        ob.x = (fast_pow_pos(ob.x, gi) - mu) * is;
        ob.y = (fast_pow_pos(ob.y, gi) - mu) * is;
        ob.z = (fast_pow_pos(ob.z, gi) - mu) * is;
        ob.w = (fast_pow_pos(ob.w, gi) - mu) * is;

        xo[i0 + i * c4] = oa;
        xo[i1 + i * c4] = ob;
    }
}

// -------------------------------------------------------------------------
extern "C" void kernel_launch(void* const* d_in, const int* in_sizes, int n_in,
                              void* d_out, int out_size)
{
    const float* x  = (const float*)d_in[0];
    const float* W1 = (const float*)d_in[1];
    const float* b1 = (const float*)d_in[2];
    const float* W2 = (const float*)d_in[3];
    float* out = (float*)d_out;

    pool_kernel<<<PGRID, PTHREADS>>>(x);
    mlp_kernel<<<B, HIDDEN>>>(W1, b1, W2);
    transform_kernel<<<B * TCTA_IMG, TBLK>>>(x, out);
}

// round 13
// speedup vs baseline: 1.5234x; 1.1179x over previous
#include <cuda_runtime.h>
#include <math.h>

#define B    32
#define C    3
#define H    640
#define W    640
#define POOL 8
#define BLK  80                  // H/POOL = rows per pool-row block
#define HW   (H * W)             // 409600
#define HIDDEN 64
#define FEAT   (C * POOL * POOL) // 192
#define NPARAM (C * C + 2 * C)   // 15

#define W4      (W / 4)          // 160 float4 per image row
#define ROWGRPS 2                // row-groups per CTA pass
#define PTHREADS (ROWGRPS * W4)  // 320 threads in pool kernel
#define PGRID   (B * C * POOL)   // 768 CTAs

// Transform tiling: 256 threads x 2 float4-groups per thread
#define TBLK      256
#define TGRP      2
#define TCHUNK    (TBLK * TGRP)          // 512 float4 per CTA
#define TCTA_IMG  (HW / 4 / TCHUNK)      // 200 CTAs per image

// Scratch (no allocations allowed)
__device__ float g_pooled[B * FEAT];
__device__ float g_params[B * NPARAM];

__constant__ float c_mean[3]    = {0.485f, 0.456f, 0.406f};
__constant__ float c_invstd[3]  = {1.0f / 0.229f, 1.0f / 0.224f, 1.0f / 0.225f};

// Guaranteed-MUFU fast pow for strictly-positive base: 2^(g * log2(x))
__device__ __forceinline__ float fast_pow_pos(float x, float g)
{
    float l, r;
    asm("lg2.approx.f32 %0, %1;" : "=f"(l) : "f"(x));
    l *= g;
    asm("ex2.approx.f32 %0, %1;" : "=f"(r) : "f"(l));
    return r;
}

// -------------------------------------------------------------------------
// Kernel 1: block means. One CTA per (b, ch, pool_row): 80 rows x 640 cols.
// 320 threads = 2 row-groups x 160 float4-cols; fixed column per thread;
// 40 loads as 20 independent pairs (2 accumulators) for ILP.
// Reduce via smem + 8-thread serial sum (deterministic, atomic-free).
// -------------------------------------------------------------------------
__global__ void __launch_bounds__(PTHREADS) pool_kernel(const float* __restrict__ x)
{
    const int blk = blockIdx.x;
    const int pr  = blk % POOL;
    const int ch  = (blk / POOL) % C;
    const int b   = blk / (POOL * C);
    const int tid = threadIdx.x;

    const int col4 = tid % W4;       // 0..159  (fixed per thread)
    const int rg   = tid / W4;       // 0..1    (fixed per thread)

    const float4* __restrict__ base = reinterpret_cast<const float4*>(
        x + ((size_t)(b * C + ch)) * HW + (size_t)pr * BLK * W) + (size_t)rg * W4 + col4;

    float s0 = 0.0f, s1 = 0.0f;
    #pragma unroll 10
    for (int r = 0; r < BLK / ROWGRPS; r += 2) {   // 40 rows -> 20 pairs
        float4 a = base[(size_t)r       * (ROWGRPS * W4)];
        float4 c = base[(size_t)(r + 1) * (ROWGRPS * W4)];
        s0 += (a.x + a.y) + (a.z + a.w);
        s1 += (c.x + c.y) + (c.z + c.w);
    }
    const float sum = s0 + s1;

    __shared__ float psum[PTHREADS];
    psum[tid] = sum;
    __syncthreads();

    if (tid < POOL) {
        // pool-col tid owns col4 in [tid*20, tid*20+20), both row-groups
        float s = 0.0f;
        #pragma unroll
        for (int g = 0; g < ROWGRPS; ++g) {
            const int base_i = g * W4 + tid * (BLK / 4);
            #pragma unroll
            for (int j = 0; j < BLK / 4; ++j)      // 20 partials
                s += psum[base_i + j];
        }
        g_pooled[b * FEAT + ch * (POOL * POOL) + pr * POOL + tid] =
            s * (1.0f / (BLK * BLK));
    }
}

// -------------------------------------------------------------------------
// Kernel 2: per-sample MLP, latency-optimized. 256 threads per sample.
// tid = j*64 + u: unit u computed by 4 threads (k-chunks of 48, fully
// unrolled -> deep front-batched coalesced W1 loads), smem partial reduce
// in fixed order. W2 preloaded to smem for layer 2.
// -------------------------------------------------------------------------
__global__ void __launch_bounds__(256) mlp_kernel(const float* __restrict__ W1,
                                                  const float* __restrict__ b1,
                                                  const float* __restrict__ W2)
{
    const int b   = blockIdx.x;
    const int tid = threadIdx.x;
    const int u   = tid & 63;    // hidden unit 0..63
    const int j   = tid >> 6;    // k-chunk 0..3 (48 k's each)

    __shared__ float feat[FEAT];
    __shared__ float part[4][HIDDEN];
    __shared__ float hid[HIDDEN];
    __shared__ float sW2[HIDDEN * NPARAM];   // 960 floats

    if (tid < FEAT) feat[tid] = g_pooled[b * FEAT + tid];
    for (int i = tid; i < HIDDEN * NPARAM; i += 256) sW2[i] = __ldg(&W2[i]);
    __syncthreads();

    // layer 1 partial: k in [j*48, j*48+48). Coalesced W1 loads across u.
    {
        const float* __restrict__ w1p = W1 + (size_t)(j * 48) * HIDDEN + u;
        const float* fp = &feat[j * 48];
        float acc = 0.0f;
        #pragma unroll
        for (int k = 0; k < 48; ++k)
            acc = fmaf(fp[k], __ldg(&w1p[(size_t)k * HIDDEN]), acc);
        part[j][u] = acc;
    }
    __syncthreads();

    if (tid < HIDDEN) {
        float s = ((part[0][tid] + part[1][tid]) + (part[2][tid] + part[3][tid]))
                  + __ldg(&b1[tid]);
        hid[tid] = fminf(fmaxf(s, 0.0f), 6.0f);
    }
    __syncthreads();

    if (tid < NPARAM) {
        float o = 0.0f;
        #pragma unroll
        for (int k = 0; k < HIDDEN; ++k)
            o = fmaf(hid[k], sW2[k * NPARAM + tid], o);
        g_params[b * NPARAM + tid] = 1.0f / (1.0f + __expf(-o));
    }
}

// -------------------------------------------------------------------------
// Kernel 3: fused color transform + pow + normalize.
// 2 float4 groups per thread (offsets tid and tid+256) -> 6 front-batched
// LDG.128, 2x MUFU/FMA ILP. grid = B * 200 = 6400 CTAs.
// -------------------------------------------------------------------------
__global__ void __launch_bounds__(TBLK) transform_kernel(const float* __restrict__ x,
                                                         float* __restrict__ out)
{
    const int b    = blockIdx.x / TCTA_IMG;
    const int base = (blockIdx.x % TCTA_IMG) * TCHUNK + threadIdx.x;

    __shared__ float prm[NPARAM];
    if (threadIdx.x < NPARAM) prm[threadIdx.x] = g_params[b * NPARAM + threadIdx.x];
    __syncthreads();

    const float4* __restrict__ xin =
        reinterpret_cast<const float4*>(x + (size_t)b * C * HW);
    float4* __restrict__ xo =
        reinterpret_cast<float4*>(out + (size_t)b * C * HW);

    const int c4 = HW / 4;                         // channel stride in float4
    const int i0 = base;
    const int i1 = base + TBLK;

    // 6 independent loads up front
    float4 a0 = xin[i0],          b0 = xin[i1];
    float4 a1 = xin[i0 + c4],     b1 = xin[i1 + c4];
    float4 a2 = xin[i0 + 2 * c4], b2 = xin[i1 + 2 * c4];

    #pragma unroll
    for (int i = 0; i < C; ++i) {
        const float m0 = prm[i * 3 + 0], m1 = prm[i * 3 + 1], m2 = prm[i * 3 + 2];
        const float bi = prm[9 + i];
        const float gi = prm[12 + i];
        const float mu = c_mean[i], is = c_invstd[i];

        float4 oa, ob;
        oa.x = fmaf(m0, a0.x, fmaf(m1, a1.x, fmaf(m2, a2.x, bi)));
        oa.y = fmaf(m0, a0.y, fmaf(m1, a1.y, fmaf(m2, a2.y, bi)));
        oa.z = fmaf(m0, a0.z, fmaf(m1, a1.z, fmaf(m2, a2.z, bi)));
        oa.w = fmaf(m0, a0.w, fmaf(m1, a1.w, fmaf(m2, a2.w, bi)));
        ob.x = fmaf(m0, b0.x, fmaf(m1, b1.x, fmaf(m2, b2.x, bi)));
        ob.y = fmaf(m0, b0.y, fmaf(m1, b1.y, fmaf(m2, b2.y, bi)));
        ob.z = fmaf(m0, b0.z, fmaf(m1, b1.z, fmaf(m2, b2.z, bi)));
        ob.w = fmaf(m0, b0.w, fmaf(m1, b1.w, fmaf(m2, b2.w, bi)));

        // base > 0 always (sigmoid-weighted combo of x in [0,1) + sigmoid bias)
        oa.x = (fast_pow_pos(oa.x, gi) - mu) * is;
        oa.y = (fast_pow_pos(oa.y, gi) - mu) * is;
        oa.z = (fast_pow_pos(oa.z, gi) - mu) * is;
        oa.w = (fast_pow_pos(oa.w, gi) - mu) * is;
        ob.x = (fast_pow_pos(ob.x, gi) - mu) * is;
        ob.y = (fast_pow_pos(ob.y, gi) - mu) * is;
        ob.z = (fast_pow_pos(ob.z, gi) - mu) * is;
        ob.w = (fast_pow_pos(ob.w, gi) - mu) * is;

        xo[i0 + i * c4] = oa;
        xo[i1 + i * c4] = ob;
    }
}

// -------------------------------------------------------------------------
extern "C" void kernel_launch(void* const* d_in, const int* in_sizes, int n_in,
                              void* d_out, int out_size)
{
    const float* x  = (const float*)d_in[0];
    const float* W1 = (const float*)d_in[1];
    const float* b1 = (const float*)d_in[2];
    const float* W2 = (const float*)d_in[3];
    float* out = (float*)d_out;

    pool_kernel<<<PGRID, PTHREADS>>>(x);
    mlp_kernel<<<B, 256>>>(W1, b1, W2);
    transform_kernel<<<B * TCTA_IMG, TBLK>>>(x, out);
}